// round 16
// baseline (speedup 1.0000x reference)
#include <cuda_runtime.h>
#include <cuda_fp16.h>
#include <cstdint>

// ---------------- problem constants ----------------
#define N_ATT   512
#define N_DEC   1024
#define N_ENC2  1024
#define N_BATCH 32
#define N_SEQ   2048
#define N_ROWS  (N_BATCH * N_SEQ)   // 65536

// ---------------- device scratch (static globals; no runtime allocation) ----------------
__device__ __half g_encH[(size_t)N_ROWS * N_ENC2];  // fp16 copy of encoder (128 MB)
__device__ __half g_UTH[N_ATT * N_ENC2];            // U_w transposed fp16: [n][k]
__device__ float  g_WsUb[N_BATCH * N_ATT];          // dec@W_w + W_b + U_b
__device__ float  g_energy[N_ROWS];
__device__ int    g_cnt[N_BATCH];                   // per-batch CTA-arrival counters

// ---------------- helpers (plain sm_80+ PTX only) ----------------
__device__ __forceinline__ uint32_t smem_u32(const void* p) {
    uint32_t a;
    asm("{ .reg .u64 t; cvta.to.shared.u64 t, %1; cvt.u32.u64 %0, t; }"
        : "=r"(a) : "l"(p));
    return a;
}

__device__ __forceinline__ void cp16(uint32_t dst, const void* src) {
    asm volatile("cp.async.cg.shared.global [%0], [%1], 16;"
                 :: "r"(dst), "l"(src) : "memory");
}
__device__ __forceinline__ void cp_commit() {
    asm volatile("cp.async.commit_group;" ::: "memory");
}
template <int N>
__device__ __forceinline__ void cp_wait() {
    asm volatile("cp.async.wait_group %0;" :: "n"(N) : "memory");
}

__device__ __forceinline__ void ldsm4(uint32_t addr, uint32_t& r0, uint32_t& r1,
                                      uint32_t& r2, uint32_t& r3) {
    asm volatile("ldmatrix.sync.aligned.m8n8.x4.shared.b16 {%0,%1,%2,%3}, [%4];"
                 : "=r"(r0), "=r"(r1), "=r"(r2), "=r"(r3) : "r"(addr));
}

__device__ __forceinline__ void mma_f16(float* d, const uint32_t* a, const uint32_t* b) {
    asm volatile(
        "mma.sync.aligned.m16n8k16.row.col.f32.f16.f16.f32 "
        "{%0,%1,%2,%3}, {%4,%5,%6,%7}, {%8,%9}, {%0,%1,%2,%3};"
        : "+f"(d[0]), "+f"(d[1]), "+f"(d[2]), "+f"(d[3])
        : "r"(a[0]), "r"(a[1]), "r"(a[2]), "r"(a[3]), "r"(b[0]), "r"(b[1]));
}

// accurate tanh: 1 - 2/(exp(2x)+1) via ex2.approx + rcp.approx (~1e-6 err)
__device__ __forceinline__ float tanh_acc(float x) {
    float e, r;
    asm("ex2.approx.f32 %0, %1;" : "=f"(e) : "f"(x * 2.8853900817779268f));
    asm("rcp.approx.f32 %0, %1;" : "=f"(r) : "f"(e + 1.0f));
    return 1.0f - 2.0f * r;
}

// ---------------- kernel A: fused prep (transpose + wsb + counter reset + conv) ----------------
// Heterogeneous 256-thread blocks, tiny work first (wave-1) so it hides under conv:
//   bid [0, 512)      : U_w transpose -> g_UTH (fp16)
//   bid [512, 576)    : g_WsUb = dec @ W_w + W_b + U_b   (R9-proven (2,32) decomposition)
//   bid 576           : reset g_cnt
//   bid [577, 16961)  : fp32 -> fp16 encoder conversion (6.2-6.7 TB/s measured)
#define PREP_CONV_BASE 577
#define PREP_GRID      (PREP_CONV_BASE + (N_ROWS * (N_ENC2 / 4)) / 1024)

__global__ void prep_kernel(const float4* __restrict__ encf4,
                            const float* __restrict__ dec,
                            const float* __restrict__ Ww,
                            const float* __restrict__ Wb,
                            const float* __restrict__ Ub,
                            const float* __restrict__ Uw) {
    int bid = blockIdx.x;
    int tid = threadIdx.x;

    if (bid < 512) {
        // ---- U_w transpose (grid was (16,32), block (32,8)) ----
        __shared__ float tile[32][33];
        int bx = bid & 15, by = bid >> 4;
        int n0 = bx * 32, k0 = by * 32;
        int tx = tid & 31, ty = tid >> 5;
        #pragma unroll
        for (int j = 0; j < 32; j += 8)
            tile[ty + j][tx] = Uw[(size_t)(k0 + ty + j) * N_ATT + n0 + tx];
        __syncthreads();
        #pragma unroll
        for (int j = 0; j < 32; j += 8)
            g_UTH[(size_t)(n0 + ty + j) * N_ENC2 + k0 + tx] =
                __float2half_rn(tile[tx][ty + j]);
        return;
    }
    if (bid < 576) {
        // ---- wsb (grid was (2,32)) ----
        int t = bid - 512;
        int a = (t & 1) * 256 + tid;
        int b = t >> 1;
        const float* dr = dec + (size_t)b * N_DEC;
        float a0 = 0.f, a1 = 0.f, a2 = 0.f, a3 = 0.f;
        #pragma unroll 4
        for (int k = 0; k < N_DEC; k += 4) {
            a0 = fmaf(dr[k + 0], Ww[(size_t)(k + 0) * N_ATT + a], a0);
            a1 = fmaf(dr[k + 1], Ww[(size_t)(k + 1) * N_ATT + a], a1);
            a2 = fmaf(dr[k + 2], Ww[(size_t)(k + 2) * N_ATT + a], a2);
            a3 = fmaf(dr[k + 3], Ww[(size_t)(k + 3) * N_ATT + a], a3);
        }
        g_WsUb[(size_t)b * N_ATT + a] = (a0 + a1) + (a2 + a3) + Wb[a] + Ub[a];
        return;
    }
    if (bid == 576) {
        if (tid < N_BATCH) g_cnt[tid] = 0;
        return;
    }

    // ---- conv (R10-tuned) ----
    size_t base = (size_t)(bid - PREP_CONV_BASE) * 1024 + tid;
    float4 v0 = encf4[base];
    float4 v1 = encf4[base + 256];
    float4 v2 = encf4[base + 512];
    float4 v3 = encf4[base + 768];
    uint2* dst = reinterpret_cast<uint2*>(g_encH);
    __half2 a0 = __floats2half2_rn(v0.x, v0.y), a1 = __floats2half2_rn(v0.z, v0.w);
    __half2 b0 = __floats2half2_rn(v1.x, v1.y), b1 = __floats2half2_rn(v1.z, v1.w);
    __half2 c0 = __floats2half2_rn(v2.x, v2.y), c1 = __floats2half2_rn(v2.z, v2.w);
    __half2 d0 = __floats2half2_rn(v3.x, v3.y), d1 = __floats2half2_rn(v3.z, v3.w);
    dst[base]       = make_uint2(*(uint32_t*)&a0, *(uint32_t*)&a1);
    dst[base + 256] = make_uint2(*(uint32_t*)&b0, *(uint32_t*)&b1);
    dst[base + 512] = make_uint2(*(uint32_t*)&c0, *(uint32_t*)&c1);
    dst[base + 768] = make_uint2(*(uint32_t*)&d0, *(uint32_t*)&d1);
}

// ---------------- kernel B: fp16 mma.sync GEMM + energy + fused last-CTA softmax ----------------
// (Hot loop byte-identical to the R4/R9-proven 234-236us configuration.)
// 512 CTAs x 256 thr, 2 CTAs/SM (regs capped at 128 via launch_bounds).
// CTA = 128 rows x 512 cols done as FOUR N=128 passes (acc 64 f32/thread).
// K-tile 64 fp16 (128B rows, XOR-swizzled), 3-stage cp.async pipeline.
// Tail: 16 CTAs/batch; the last arrival (threadfence+atomic counter) runs that
// batch's softmax (identical algorithm to the old standalone kernel).
#define KT        64
#define NSTAGE    3
#define STG_A     16384                 // 128 rows * 128B
#define STG_B     16384                 // 128 n-rows * 128B
#define STG_BYTES (STG_A + STG_B)
#define HDR       5120                  // e_sm(512) + wsb(2048) + vv(2048) + pad
#define SMEM_MAIN (HDR + NSTAGE * STG_BYTES)   // 103424 B -> 2 CTAs/SM
#define NTILES    64                    // 4 passes * 16 K-tiles

struct LoadCtx {
    uint32_t sb;
    int tid, row_base;
};

__device__ __forceinline__ void load_tile(const LoadCtx& L, int tc) {
    int pass = tc >> 4, kt = tc & 15;
    uint32_t st = L.sb + HDR + (tc % NSTAGE) * STG_BYTES;
    const __half* Asrc = g_encH + (size_t)L.row_base * N_ENC2 + kt * KT;
    #pragma unroll
    for (int i = 0; i < 4; i++) {
        int id = L.tid + i * 256;
        int r = id >> 3, c = id & 7;
        cp16(st + r * 128 + (((uint32_t)(c ^ (r & 7))) << 4),
             Asrc + (size_t)r * N_ENC2 + c * 8);
    }
    const __half* Bsrc = g_UTH + (size_t)(pass * 128) * N_ENC2 + kt * KT;
    uint32_t stB = st + STG_A;
    #pragma unroll
    for (int i = 0; i < 4; i++) {
        int id = L.tid + i * 256;
        int n = id >> 3, c = id & 7;
        cp16(stB + n * 128 + (((uint32_t)(c ^ (n & 7))) << 4),
             Bsrc + (size_t)n * N_ENC2 + c * 8);
    }
    cp_commit();
}

__global__ void __launch_bounds__(256, 2)
attn_energy_kernel(const float* __restrict__ vw, float* __restrict__ out) {
    extern __shared__ char smem[];
    uint32_t sb = smem_u32(smem);
    int tid = threadIdx.x;
    int lane = tid & 31, wid = tid >> 5;
    int warpM = wid >> 2, warpN = wid & 3;
    int row_base = blockIdx.x * 128;
    int b = row_base >> 11;

    float* e_sm = (float*)smem;              // [128]
    float* wsb  = (float*)(smem + 512);      // [512]
    float* vv   = (float*)(smem + 2560);     // [512]
    if (tid < 128) e_sm[tid] = 0.f;
    for (int i = tid; i < N_ATT; i += 256) {
        wsb[i] = g_WsUb[(size_t)b * N_ATT + i];
        vv[i]  = vw[i];
    }

    LoadCtx L{sb, tid, row_base};

    // prologue: 2 tiles in flight
    load_tile(L, 0); load_tile(L, 1);

    // per-thread ldmatrix address components
    int arow0 = warpM * 64 + (lane & 7) + ((lane >> 3) & 1) * 8;  // + mb*16
    int ach   = (lane >> 4) & 1;
    int brow0 = warpN * 32 + (lane & 7) + ((lane >> 4) & 1) * 8;  // + p*16
    int bch   = (lane >> 3) & 1;
    int g = lane >> 2, t = lane & 3;

    #pragma unroll 1
    for (int pass = 0; pass < 4; pass++) {
        float acc[4][4][4];
        #pragma unroll
        for (int mb = 0; mb < 4; mb++)
            #pragma unroll
            for (int nb = 0; nb < 4; nb++)
                #pragma unroll
                for (int c = 0; c < 4; c++) acc[mb][nb][c] = 0.f;

        #pragma unroll 1
        for (int kt = 0; kt < 16; kt++) {
            int tc = pass * 16 + kt;
            if (tc < NTILES - 1) cp_wait<1>(); else cp_wait<0>();
            __syncthreads();
            if (tc + 2 < NTILES) load_tile(L, tc + 2);

            uint32_t st  = sb + HDR + (tc % NSTAGE) * STG_BYTES;
            uint32_t stB = st + STG_A;
            #pragma unroll
            for (int ks = 0; ks < 4; ks++) {       // each ks = K16
                uint32_t afr[4][4];
                #pragma unroll
                for (int mb = 0; mb < 4; mb++) {
                    int r = arow0 + mb * 16;
                    uint32_t addr = st + r * 128 +
                        (((uint32_t)((2 * ks + ach) ^ (r & 7))) << 4);
                    ldsm4(addr, afr[mb][0], afr[mb][1], afr[mb][2], afr[mb][3]);
                }
                uint32_t bfr[4][2];
                #pragma unroll
                for (int p = 0; p < 2; p++) {
                    int r = brow0 + p * 16;
                    uint32_t addr = stB + r * 128 +
                        (((uint32_t)((2 * ks + bch) ^ (r & 7))) << 4);
                    uint32_t r0, r1, r2, r3;
                    ldsm4(addr, r0, r1, r2, r3);
                    bfr[2 * p][0] = r0; bfr[2 * p][1] = r1;
                    bfr[2 * p + 1][0] = r2; bfr[2 * p + 1][1] = r3;
                }
                #pragma unroll
                for (int mb = 0; mb < 4; mb++)
                    #pragma unroll
                    for (int nb = 0; nb < 4; nb++)
                        mma_f16(acc[mb][nb], afr[mb], bfr[nb]);
            }
        }

        // fused epilogue: energy += v . tanh(acc + wsb); overlaps in-flight cp.async
        #pragma unroll
        for (int mb = 0; mb < 4; mb++) {
            #pragma unroll
            for (int h = 0; h < 2; h++) {
                float rsum = 0.f;
                #pragma unroll
                for (int nb = 0; nb < 4; nb++) {
                    #pragma unroll
                    for (int c = 0; c < 2; c++) {
                        int col = pass * 128 + warpN * 32 + nb * 8 + 2 * t + c;
                        float x = acc[mb][nb][2 * h + c] + wsb[col];
                        rsum = fmaf(vv[col], tanh_acc(x), rsum);
                    }
                }
                rsum += __shfl_xor_sync(0xffffffffu, rsum, 1);
                rsum += __shfl_xor_sync(0xffffffffu, rsum, 2);
                if (t == 0)
                    atomicAdd(e_sm + warpM * 64 + mb * 16 + h * 8 + g, rsum);
            }
        }
    }
    __syncthreads();

    if (tid < 128) g_energy[row_base + tid] = e_sm[tid];

    // ---- last-CTA-per-batch softmax (threadFenceReduction pattern) ----
    __threadfence();
    __syncthreads();
    __shared__ int s_last;
    if (tid == 0) s_last = atomicAdd(&g_cnt[b], 1);
    __syncthreads();
    if (s_last == 15) {
        __threadfence();
        const float* e = g_energy + (size_t)b * N_SEQ;
        float v[8];
        float mx = -1e30f;
        #pragma unroll
        for (int i = 0; i < 8; i++) { v[i] = e[tid + i * 256]; mx = fmaxf(mx, v[i]); }
        #pragma unroll
        for (int o = 16; o; o >>= 1) mx = fmaxf(mx, __shfl_xor_sync(0xFFFFFFFFu, mx, o));
        float* redm = (float*)smem;          // reuse e_sm region (post-sync)
        float* reds = (float*)(smem + 64);
        if ((tid & 31) == 0) redm[tid >> 5] = mx;
        __syncthreads();
        float m2 = redm[0];
        #pragma unroll
        for (int i = 1; i < 8; i++) m2 = fmaxf(m2, redm[i]);
        float sum = 0.f;
        #pragma unroll
        for (int i = 0; i < 8; i++) { v[i] = expf(v[i] - m2); sum += v[i]; }
        #pragma unroll
        for (int o = 16; o; o >>= 1) sum += __shfl_xor_sync(0xFFFFFFFFu, sum, o);
        if ((tid & 31) == 0) reds[tid >> 5] = sum;
        __syncthreads();
        float s2 = 0.f;
        #pragma unroll
        for (int i = 0; i < 8; i++) s2 += reds[i];
        float inv = 1.f / s2;
        #pragma unroll
        for (int i = 0; i < 8; i++)
            out[(size_t)b * N_SEQ + tid + i * 256] = v[i] * inv;
    }
}

// ---------------- launch: 2 kernels total ----------------
extern "C" void kernel_launch(void* const* d_in, const int* in_sizes, int n_in,
                              void* d_out, int out_size) {
    const float* dec = (const float*)d_in[0];   // (32, 1024)
    const float* enc = (const float*)d_in[1];   // (32, 2048, 1024)
    const float* Ww  = (const float*)d_in[2];   // (1024, 512)
    const float* Wb  = (const float*)d_in[3];   // (512,)
    const float* Uw  = (const float*)d_in[4];   // (1024, 512)
    const float* Ub  = (const float*)d_in[5];   // (512,)
    const float* vw  = (const float*)d_in[6];   // (512, 1)
    float* out = (float*)d_out;                 // (32, 2048)

    cudaFuncSetAttribute(attn_energy_kernel,
                         cudaFuncAttributeMaxDynamicSharedMemorySize, SMEM_MAIN);

    prep_kernel<<<PREP_GRID, 256>>>((const float4*)enc, dec, Ww, Wb, Ub, Uw);
    attn_energy_kernel<<<N_ROWS / 128, 256, SMEM_MAIN>>>(vw, out);
}

// round 17
// speedup vs baseline: 1.1530x; 1.1530x over previous
#include <cuda_runtime.h>
#include <cuda_fp16.h>
#include <cstdint>

// ---------------- problem constants ----------------
#define N_ATT   512
#define N_DEC   1024
#define N_ENC2  1024
#define N_BATCH 32
#define N_SEQ   2048
#define N_ROWS  (N_BATCH * N_SEQ)   // 65536

// ---------------- device scratch (static globals; no runtime allocation) ----------------
__device__ __half g_encH[(size_t)N_ROWS * N_ENC2];  // fp16 copy of encoder (128 MB)
__device__ __half g_UTH[N_ATT * N_ENC2];            // U_w transposed fp16: [n][k]
__device__ float  g_WsUb[N_BATCH * N_ATT];          // dec@W_w + W_b + U_b
__device__ float  g_energy[N_ROWS];

// ---------------- helpers (plain sm_80+ PTX only) ----------------
__device__ __forceinline__ uint32_t smem_u32(const void* p) {
    uint32_t a;
    asm("{ .reg .u64 t; cvta.to.shared.u64 t, %1; cvt.u32.u64 %0, t; }"
        : "=r"(a) : "l"(p));
    return a;
}

__device__ __forceinline__ void cp16(uint32_t dst, const void* src) {
    asm volatile("cp.async.cg.shared.global [%0], [%1], 16;"
                 :: "r"(dst), "l"(src) : "memory");
}
__device__ __forceinline__ void cp_commit() {
    asm volatile("cp.async.commit_group;" ::: "memory");
}
template <int N>
__device__ __forceinline__ void cp_wait() {
    asm volatile("cp.async.wait_group %0;" :: "n"(N) : "memory");
}

__device__ __forceinline__ void ldsm4(uint32_t addr, uint32_t& r0, uint32_t& r1,
                                      uint32_t& r2, uint32_t& r3) {
    asm volatile("ldmatrix.sync.aligned.m8n8.x4.shared.b16 {%0,%1,%2,%3}, [%4];"
                 : "=r"(r0), "=r"(r1), "=r"(r2), "=r"(r3) : "r"(addr));
}

__device__ __forceinline__ void mma_f16(float* d, const uint32_t* a, const uint32_t* b) {
    asm volatile(
        "mma.sync.aligned.m16n8k16.row.col.f32.f16.f16.f32 "
        "{%0,%1,%2,%3}, {%4,%5,%6,%7}, {%8,%9}, {%0,%1,%2,%3};"
        : "+f"(d[0]), "+f"(d[1]), "+f"(d[2]), "+f"(d[3])
        : "r"(a[0]), "r"(a[1]), "r"(a[2]), "r"(a[3]), "r"(b[0]), "r"(b[1]));
}

// accurate tanh: 1 - 2/(exp(2x)+1) via ex2.approx + rcp.approx (~1e-6 err)
__device__ __forceinline__ float tanh_acc(float x) {
    float e, r;
    asm("ex2.approx.f32 %0, %1;" : "=f"(e) : "f"(x * 2.8853900817779268f));
    asm("rcp.approx.f32 %0, %1;" : "=f"(r) : "f"(e + 1.0f));
    return 1.0f - 2.0f * r;
}

// ---------------- kernel A: fused prep (transpose + wsb + conv) ----------------
// Heterogeneous 256-thread blocks; tiny work gets the lowest bids (wave-1) and
// hides entirely under conv's 52us DRAM-bound window (R16-verified).
//   bid [0, 512)      : U_w transpose -> g_UTH (fp16)
//   bid [512, 576)    : g_WsUb = dec @ W_w + W_b + U_b   (R9-proven (2,32) split)
//   bid [576, 16960)  : fp32 -> fp16 encoder conversion (6.2-6.7 TB/s measured)
#define PREP_CONV_BASE 576
#define PREP_GRID      (PREP_CONV_BASE + (N_ROWS * (N_ENC2 / 4)) / 1024)

__global__ void prep_kernel(const float4* __restrict__ encf4,
                            const float* __restrict__ dec,
                            const float* __restrict__ Ww,
                            const float* __restrict__ Wb,
                            const float* __restrict__ Ub,
                            const float* __restrict__ Uw) {
    int bid = blockIdx.x;
    int tid = threadIdx.x;

    if (bid < 512) {
        // ---- U_w transpose (was grid (16,32), block (32,8)) ----
        __shared__ float tile[32][33];
        int bx = bid & 15, by = bid >> 4;
        int n0 = bx * 32, k0 = by * 32;
        int tx = tid & 31, ty = tid >> 5;
        #pragma unroll
        for (int j = 0; j < 32; j += 8)
            tile[ty + j][tx] = Uw[(size_t)(k0 + ty + j) * N_ATT + n0 + tx];
        __syncthreads();
        #pragma unroll
        for (int j = 0; j < 32; j += 8)
            g_UTH[(size_t)(n0 + ty + j) * N_ENC2 + k0 + tx] =
                __float2half_rn(tile[tx][ty + j]);
        return;
    }
    if (bid < 576) {
        // ---- wsb (was grid (2,32)) ----
        int t = bid - 512;
        int a = (t & 1) * 256 + tid;
        int b = t >> 1;
        const float* dr = dec + (size_t)b * N_DEC;
        float a0 = 0.f, a1 = 0.f, a2 = 0.f, a3 = 0.f;
        #pragma unroll 4
        for (int k = 0; k < N_DEC; k += 4) {
            a0 = fmaf(dr[k + 0], Ww[(size_t)(k + 0) * N_ATT + a], a0);
            a1 = fmaf(dr[k + 1], Ww[(size_t)(k + 1) * N_ATT + a], a1);
            a2 = fmaf(dr[k + 2], Ww[(size_t)(k + 2) * N_ATT + a], a2);
            a3 = fmaf(dr[k + 3], Ww[(size_t)(k + 3) * N_ATT + a], a3);
        }
        g_WsUb[(size_t)b * N_ATT + a] = (a0 + a1) + (a2 + a3) + Wb[a] + Ub[a];
        return;
    }

    // ---- conv (R10-tuned) ----
    size_t base = (size_t)(bid - PREP_CONV_BASE) * 1024 + tid;
    float4 v0 = encf4[base];
    float4 v1 = encf4[base + 256];
    float4 v2 = encf4[base + 512];
    float4 v3 = encf4[base + 768];
    uint2* dst = reinterpret_cast<uint2*>(g_encH);
    __half2 a0 = __floats2half2_rn(v0.x, v0.y), a1 = __floats2half2_rn(v0.z, v0.w);
    __half2 b0 = __floats2half2_rn(v1.x, v1.y), b1 = __floats2half2_rn(v1.z, v1.w);
    __half2 c0 = __floats2half2_rn(v2.x, v2.y), c1 = __floats2half2_rn(v2.z, v2.w);
    __half2 d0 = __floats2half2_rn(v3.x, v3.y), d1 = __floats2half2_rn(v3.z, v3.w);
    dst[base]       = make_uint2(*(uint32_t*)&a0, *(uint32_t*)&a1);
    dst[base + 256] = make_uint2(*(uint32_t*)&b0, *(uint32_t*)&b1);
    dst[base + 512] = make_uint2(*(uint32_t*)&c0, *(uint32_t*)&c1);
    dst[base + 768] = make_uint2(*(uint32_t*)&d0, *(uint32_t*)&d1);
}

// ---------------- kernel B: fp16 mma.sync GEMM + fused energy epilogue ----------------
// BYTE-IDENTICAL to the R9/R15-proven 236us configuration. NO extra tail code —
// R16 proved that adding a cold softmax tail under the 128-reg cap spills the
// hot loop (236 -> 287us). Do not fuse anything else into this kernel.
#define KT        64
#define NSTAGE    3
#define STG_A     16384                 // 128 rows * 128B
#define STG_B     16384                 // 128 n-rows * 128B
#define STG_BYTES (STG_A + STG_B)
#define HDR       5120                  // e_sm(512) + wsb(2048) + vv(2048) + pad
#define SMEM_MAIN (HDR + NSTAGE * STG_BYTES)   // 103424 B -> 2 CTAs/SM
#define NTILES    64                    // 4 passes * 16 K-tiles

struct LoadCtx {
    uint32_t sb;
    int tid, row_base;
};

__device__ __forceinline__ void load_tile(const LoadCtx& L, int tc) {
    int pass = tc >> 4, kt = tc & 15;
    uint32_t st = L.sb + HDR + (tc % NSTAGE) * STG_BYTES;
    const __half* Asrc = g_encH + (size_t)L.row_base * N_ENC2 + kt * KT;
    #pragma unroll
    for (int i = 0; i < 4; i++) {
        int id = L.tid + i * 256;
        int r = id >> 3, c = id & 7;
        cp16(st + r * 128 + (((uint32_t)(c ^ (r & 7))) << 4),
             Asrc + (size_t)r * N_ENC2 + c * 8);
    }
    const __half* Bsrc = g_UTH + (size_t)(pass * 128) * N_ENC2 + kt * KT;
    uint32_t stB = st + STG_A;
    #pragma unroll
    for (int i = 0; i < 4; i++) {
        int id = L.tid + i * 256;
        int n = id >> 3, c = id & 7;
        cp16(stB + n * 128 + (((uint32_t)(c ^ (n & 7))) << 4),
             Bsrc + (size_t)n * N_ENC2 + c * 8);
    }
    cp_commit();
}

__global__ void __launch_bounds__(256, 2)
attn_energy_kernel(const float* __restrict__ vw) {
    extern __shared__ char smem[];
    uint32_t sb = smem_u32(smem);
    int tid = threadIdx.x;
    int lane = tid & 31, wid = tid >> 5;
    int warpM = wid >> 2, warpN = wid & 3;
    int row_base = blockIdx.x * 128;
    int b = row_base >> 11;

    float* e_sm = (float*)smem;              // [128]
    float* wsb  = (float*)(smem + 512);      // [512]
    float* vv   = (float*)(smem + 2560);     // [512]
    if (tid < 128) e_sm[tid] = 0.f;
    for (int i = tid; i < N_ATT; i += 256) {
        wsb[i] = g_WsUb[(size_t)b * N_ATT + i];
        vv[i]  = vw[i];
    }

    LoadCtx L{sb, tid, row_base};

    // prologue: 2 tiles in flight
    load_tile(L, 0); load_tile(L, 1);

    // per-thread ldmatrix address components
    int arow0 = warpM * 64 + (lane & 7) + ((lane >> 3) & 1) * 8;  // + mb*16
    int ach   = (lane >> 4) & 1;
    int brow0 = warpN * 32 + (lane & 7) + ((lane >> 4) & 1) * 8;  // + p*16
    int bch   = (lane >> 3) & 1;
    int g = lane >> 2, t = lane & 3;

    #pragma unroll 1
    for (int pass = 0; pass < 4; pass++) {
        float acc[4][4][4];
        #pragma unroll
        for (int mb = 0; mb < 4; mb++)
            #pragma unroll
            for (int nb = 0; nb < 4; nb++)
                #pragma unroll
                for (int c = 0; c < 4; c++) acc[mb][nb][c] = 0.f;

        #pragma unroll 1
        for (int kt = 0; kt < 16; kt++) {
            int tc = pass * 16 + kt;
            if (tc < NTILES - 1) cp_wait<1>(); else cp_wait<0>();
            __syncthreads();
            if (tc + 2 < NTILES) load_tile(L, tc + 2);

            uint32_t st  = sb + HDR + (tc % NSTAGE) * STG_BYTES;
            uint32_t stB = st + STG_A;
            #pragma unroll
            for (int ks = 0; ks < 4; ks++) {       // each ks = K16
                uint32_t afr[4][4];
                #pragma unroll
                for (int mb = 0; mb < 4; mb++) {
                    int r = arow0 + mb * 16;
                    uint32_t addr = st + r * 128 +
                        (((uint32_t)((2 * ks + ach) ^ (r & 7))) << 4);
                    ldsm4(addr, afr[mb][0], afr[mb][1], afr[mb][2], afr[mb][3]);
                }
                uint32_t bfr[4][2];
                #pragma unroll
                for (int p = 0; p < 2; p++) {
                    int r = brow0 + p * 16;
                    uint32_t addr = stB + r * 128 +
                        (((uint32_t)((2 * ks + bch) ^ (r & 7))) << 4);
                    uint32_t r0, r1, r2, r3;
                    ldsm4(addr, r0, r1, r2, r3);
                    bfr[2 * p][0] = r0; bfr[2 * p][1] = r1;
                    bfr[2 * p + 1][0] = r2; bfr[2 * p + 1][1] = r3;
                }
                #pragma unroll
                for (int mb = 0; mb < 4; mb++)
                    #pragma unroll
                    for (int nb = 0; nb < 4; nb++)
                        mma_f16(acc[mb][nb], afr[mb], bfr[nb]);
            }
        }

        // fused epilogue: energy += v . tanh(acc + wsb); overlaps in-flight cp.async
        #pragma unroll
        for (int mb = 0; mb < 4; mb++) {
            #pragma unroll
            for (int h = 0; h < 2; h++) {
                float rsum = 0.f;
                #pragma unroll
                for (int nb = 0; nb < 4; nb++) {
                    #pragma unroll
                    for (int c = 0; c < 2; c++) {
                        int col = pass * 128 + warpN * 32 + nb * 8 + 2 * t + c;
                        float x = acc[mb][nb][2 * h + c] + wsb[col];
                        rsum = fmaf(vv[col], tanh_acc(x), rsum);
                    }
                }
                rsum += __shfl_xor_sync(0xffffffffu, rsum, 1);
                rsum += __shfl_xor_sync(0xffffffffu, rsum, 2);
                if (t == 0)
                    atomicAdd(e_sm + warpM * 64 + mb * 16 + h * 8 + g, rsum);
            }
        }
    }
    __syncthreads();

    if (tid < 128) g_energy[row_base + tid] = e_sm[tid];
}

// ---------------- kernel C: softmax over S=2048 per batch row ----------------
__global__ void softmax_kernel(float* __restrict__ out) {
    int b = blockIdx.x;
    int tid = threadIdx.x;
    const float* e = g_energy + (size_t)b * N_SEQ;
    float v[8];
    float mx = -1e30f;
    #pragma unroll
    for (int i = 0; i < 8; i++) { v[i] = e[tid + i * 256]; mx = fmaxf(mx, v[i]); }
    #pragma unroll
    for (int o = 16; o; o >>= 1) mx = fmaxf(mx, __shfl_xor_sync(0xFFFFFFFFu, mx, o));
    __shared__ float redm[8], reds[8];
    if ((tid & 31) == 0) redm[tid >> 5] = mx;
    __syncthreads();
    float m2 = redm[0];
    #pragma unroll
    for (int i = 1; i < 8; i++) m2 = fmaxf(m2, redm[i]);
    float sum = 0.f;
    #pragma unroll
    for (int i = 0; i < 8; i++) { v[i] = expf(v[i] - m2); sum += v[i]; }
    #pragma unroll
    for (int o = 16; o; o >>= 1) sum += __shfl_xor_sync(0xFFFFFFFFu, sum, o);
    if ((tid & 31) == 0) reds[tid >> 5] = sum;
    __syncthreads();
    float s2 = 0.f;
    #pragma unroll
    for (int i = 0; i < 8; i++) s2 += reds[i];
    float inv = 1.f / s2;
    #pragma unroll
    for (int i = 0; i < 8; i++) out[(size_t)b * N_SEQ + tid + i * 256] = v[i] * inv;
}

// ---------------- launch: 3 kernels ----------------
extern "C" void kernel_launch(void* const* d_in, const int* in_sizes, int n_in,
                              void* d_out, int out_size) {
    const float* dec = (const float*)d_in[0];   // (32, 1024)
    const float* enc = (const float*)d_in[1];   // (32, 2048, 1024)
    const float* Ww  = (const float*)d_in[2];   // (1024, 512)
    const float* Wb  = (const float*)d_in[3];   // (512,)
    const float* Uw  = (const float*)d_in[4];   // (1024, 512)
    const float* Ub  = (const float*)d_in[5];   // (512,)
    const float* vw  = (const float*)d_in[6];   // (512, 1)
    float* out = (float*)d_out;                 // (32, 2048)

    cudaFuncSetAttribute(attn_energy_kernel,
                         cudaFuncAttributeMaxDynamicSharedMemorySize, SMEM_MAIN);

    prep_kernel<<<PREP_GRID, 256>>>((const float4*)enc, dec, Ww, Wb, Ub, Uw);
    attn_energy_kernel<<<N_ROWS / 128, 256, SMEM_MAIN>>>(vw);
    softmax_kernel<<<N_BATCH, 256>>>(out);
}